// round 3
// baseline (speedup 1.0000x reference)
#include <cuda_runtime.h>
#include <cuda_bf16.h>
#include <math.h>

// Problem constants
#define BATCH 8
#define HH 64
#define WW 64
#define DD 512
#define NHEAD 16
#define DK 32
#define WS 8
#define SHIFT 4
#define TOK (BATCH*HH*WW)      // 32768
#define LAYERS 4
#define SCALE 0.17677669529663687f  // 1/sqrt(32)

// -------------------- scratch (allocation-free: __device__ globals) ------------
__device__ float g_xn [ (size_t)TOK * DD ];        // 64 MB
__device__ float g_q  [ (size_t)TOK * DD ];        // 64 MB
__device__ float g_kv [ (size_t)TOK * 2 * DD ];    // 128 MB
__device__ float g_ao [ (size_t)TOK * DD ];        // 64 MB
__device__ float g_h  [ (size_t)TOK * DD ];        // 64 MB
__device__ float g_hid[ (size_t)TOK * 4 * DD ];    // 256 MB

// -------------------- LayerNorm ------------------------------------------------
// one block per token, 128 threads, D=512 (4 elems/thread)
__global__ __launch_bounds__(128) void ln_kernel(const float* __restrict__ x,
                                                 const float* __restrict__ gamma,
                                                 const float* __restrict__ beta,
                                                 float* __restrict__ out) {
    int tok = blockIdx.x;
    int tid = threadIdx.x;
    const float* xr = x + (size_t)tok * DD;
    float v[4];
#pragma unroll
    for (int i = 0; i < 4; i++) v[i] = xr[tid + i * 128];

    __shared__ float s1[4], s2[4];
    int lane = tid & 31, warp = tid >> 5;

    float s = v[0] + v[1] + v[2] + v[3];
#pragma unroll
    for (int o = 16; o > 0; o >>= 1) s += __shfl_xor_sync(0xffffffffu, s, o);
    if (lane == 0) s1[warp] = s;
    __syncthreads();
    float mean = (s1[0] + s1[1] + s1[2] + s1[3]) * (1.0f / DD);

    float sq = 0.f;
#pragma unroll
    for (int i = 0; i < 4; i++) { float d = v[i] - mean; sq += d * d; }
#pragma unroll
    for (int o = 16; o > 0; o >>= 1) sq += __shfl_xor_sync(0xffffffffu, sq, o);
    if (lane == 0) s2[warp] = sq;
    __syncthreads();
    float var = (s2[0] + s2[1] + s2[2] + s2[3]) * (1.0f / DD);
    float rs = rsqrtf(var + 1e-5f);

    float* orow = out + (size_t)tok * DD;
#pragma unroll
    for (int i = 0; i < 4; i++) {
        int c = tid + i * 128;
        orow[c] = (v[i] - mean) * rs * gamma[c] + beta[c];
    }
}

// -------------------- GEMM: C = act(A[M,K] @ W[K,N] + bias) (+ resid) ----------
__device__ __forceinline__ float gelu_tanh(float x) {
    // jax.nn.gelu approximate=True
    float x3 = x * x * x;
    return 0.5f * x * (1.0f + tanhf(0.7978845608028654f * (x + 0.044715f * x3)));
}

__global__ __launch_bounds__(256) void gemm_kernel(const float* __restrict__ A,
                                                   const float* __restrict__ W,
                                                   const float* __restrict__ bias,
                                                   const float* __restrict__ resid,
                                                   float* __restrict__ C,
                                                   int M, int N, int K, int do_gelu) {
    const int BM = 128, BN = 128, BK = 8;
    __shared__ float As[BK][BM];
    __shared__ float Bs[BK][BN];

    int tid = threadIdx.x;
    int bm0 = blockIdx.y * BM;
    int bn0 = blockIdx.x * BN;
    int tx = tid & 15, ty = tid >> 4;

    float acc[8][8];
#pragma unroll
    for (int i = 0; i < 8; i++)
#pragma unroll
        for (int j = 0; j < 8; j++) acc[i][j] = 0.f;

    int aRow = tid >> 1, aCol = (tid & 1) * 4;       // 128 rows x 8 cols of A
    int bRow = tid >> 5, bCol = (tid & 31) * 4;      // 8 rows x 128 cols of W
    const float* Aptr = A + (size_t)(bm0 + aRow) * K + aCol;
    const float* Wptr = W + (size_t)bRow * N + bn0 + bCol;

    for (int k0 = 0; k0 < K; k0 += BK) {
        float4 av = *(const float4*)(Aptr + k0);
        As[aCol + 0][aRow] = av.x;
        As[aCol + 1][aRow] = av.y;
        As[aCol + 2][aRow] = av.z;
        As[aCol + 3][aRow] = av.w;
        float4 bv = *(const float4*)(Wptr + (size_t)k0 * N);
        *(float4*)&Bs[bRow][bCol] = bv;
        __syncthreads();
#pragma unroll
        for (int kk = 0; kk < BK; kk++) {
            float a[8], b[8];
#pragma unroll
            for (int i = 0; i < 8; i++) a[i] = As[kk][ty * 8 + i];
#pragma unroll
            for (int j = 0; j < 8; j++) b[j] = Bs[kk][tx * 8 + j];
#pragma unroll
            for (int i = 0; i < 8; i++)
#pragma unroll
                for (int j = 0; j < 8; j++) acc[i][j] += a[i] * b[j];
        }
        __syncthreads();
    }

#pragma unroll
    for (int i = 0; i < 8; i++) {
        int gr = bm0 + ty * 8 + i;
#pragma unroll
        for (int j = 0; j < 8; j++) {
            int gc = bn0 + tx * 8 + j;
            float val = acc[i][j] + bias[gc];
            if (do_gelu) val = gelu_tanh(val);
            size_t idx = (size_t)gr * N + gc;
            if (resid) val += resid[idx];
            C[idx] = val;
        }
    }
}

// -------------------- Shifted-window attention ---------------------------------
// one block per (batch, window, head); 64 threads = 64 queries
__device__ __forceinline__ int region_id(int hs, int ws) {
    int rh = (hs < HH - WS) ? 0 : (hs < HH - SHIFT) ? 1 : 2;
    int rw = (ws < WW - WS) ? 0 : (ws < WW - SHIFT) ? 1 : 2;
    return rh * 3 + rw;
}

__global__ __launch_bounds__(64) void attn_kernel(const float* __restrict__ q,
                                                  const float* __restrict__ kv,
                                                  const float* __restrict__ table, // [225,16] for this layer
                                                  float* __restrict__ out) {
    __shared__ float Ks[64 * 32];
    __shared__ float Vs[64 * 32];
    __shared__ float S[64 * 65];
    __shared__ float T[225];

    int bi = blockIdx.x;
    int nh  = bi & 15; bi >>= 4;
    int nww = bi & 7;  bi >>= 3;
    int nwh = bi & 7;  bi >>= 3;
    int b = bi;
    int tid = threadIdx.x;

    for (int i = tid; i < 225; i += 64) T[i] = table[i * NHEAD + nh];

    for (int idx = tid; idx < 64 * 32; idx += 64) {
        int e = idx >> 5, d = idx & 31;
        int h = (nwh * WS + (e >> 3) + SHIFT) & (HH - 1);
        int w = (nww * WS + (e & 7) + SHIFT) & (WW - 1);
        size_t tok = ((size_t)b * HH + h) * WW + w;
        Ks[idx] = kv[tok * (2 * DD) + nh * DK + d];
        Vs[idx] = kv[tok * (2 * DD) + DD + nh * DK + d];
    }
    __syncthreads();

    int iq = tid >> 3, jq = tid & 7;
    int h = (nwh * WS + iq + SHIFT) & (HH - 1);
    int w = (nww * WS + jq + SHIFT) & (WW - 1);
    size_t tok = ((size_t)b * HH + h) * WW + w;

    float qr[DK];
#pragma unroll
    for (int d = 0; d < DK; d++) qr[d] = q[tok * DD + nh * DK + d];

    int cq = region_id(nwh * WS + iq, nww * WS + jq);

    float rowmax = -1e30f;
    for (int k = 0; k < 64; k++) {
        int ik = k >> 3, jk = k & 7;
        float dot = 0.f;
#pragma unroll
        for (int d = 0; d < DK; d++) dot += qr[d] * Ks[k * 32 + d];
        float s = dot * SCALE + T[(iq - ik + 7) * 15 + (jq - jk + 7)];
        int ck = region_id(nwh * WS + ik, nww * WS + jk);
        if (ck != cq) s = -1e9f;
        S[tid * 65 + k] = s;
        rowmax = fmaxf(rowmax, s);
    }

    float denom = 0.f;
    for (int k = 0; k < 64; k++) {
        float e = expf(S[tid * 65 + k] - rowmax);
        S[tid * 65 + k] = e;
        denom += e;
    }
    float inv = 1.0f / denom;

    float acc[DK];
#pragma unroll
    for (int d = 0; d < DK; d++) acc[d] = 0.f;
    for (int k = 0; k < 64; k++) {
        float a = S[tid * 65 + k];
#pragma unroll
        for (int d = 0; d < DK; d++) acc[d] += a * Vs[k * 32 + d];
    }

    float* orow = out + tok * DD + nh * DK;
#pragma unroll
    for (int d = 0; d < DK; d++) orow[d] = acc[d] * inv;
}

// -------------------- driver ---------------------------------------------------
extern "C" void kernel_launch(void* const* d_in, const int* in_sizes, int n_in,
                              void* d_out, int out_size) {
    const float* x_in      = (const float*)d_in[0];
    // d_in[1] (mask) and d_in[2] (rel_index) are recomputed analytically on device
    const float* Wq        = (const float*)d_in[3];
    const float* bq        = (const float*)d_in[4];
    const float* Wkv       = (const float*)d_in[5];
    const float* bkv       = (const float*)d_in[6];
    const float* Wo        = (const float*)d_in[7];
    const float* bo        = (const float*)d_in[8];
    const float* rel_table = (const float*)d_in[9];
    const float* ln1_g     = (const float*)d_in[10];
    const float* ln1_b     = (const float*)d_in[11];
    const float* ln2_g     = (const float*)d_in[12];
    const float* ln2_b     = (const float*)d_in[13];
    const float* W1        = (const float*)d_in[14];
    const float* b1        = (const float*)d_in[15];
    const float* W2        = (const float*)d_in[16];
    const float* b2        = (const float*)d_in[17];

    float* x = (float*)d_out;   // resident x buffer lives in d_out

    float *xn, *qb, *kvb, *ao, *hb, *hid;
    cudaGetSymbolAddress((void**)&xn,  g_xn);
    cudaGetSymbolAddress((void**)&qb,  g_q);
    cudaGetSymbolAddress((void**)&kvb, g_kv);
    cudaGetSymbolAddress((void**)&ao,  g_ao);
    cudaGetSymbolAddress((void**)&hb,  g_h);
    cudaGetSymbolAddress((void**)&hid, g_hid);

    cudaMemcpyAsync(x, x_in, (size_t)TOK * DD * sizeof(float),
                    cudaMemcpyDeviceToDevice, 0);

    for (int l = 0; l < LAYERS; l++) {
        const float* Wq_l  = Wq  + (size_t)l * DD * DD;
        const float* bq_l  = bq  + (size_t)l * DD;
        const float* Wkv_l = Wkv + (size_t)l * DD * 2 * DD;
        const float* bkv_l = bkv + (size_t)l * 2 * DD;
        const float* Wo_l  = Wo  + (size_t)l * DD * DD;
        const float* bo_l  = bo  + (size_t)l * DD;
        const float* tbl_l = rel_table + (size_t)l * 225 * NHEAD;
        const float* W1_l  = W1  + (size_t)l * DD * 4 * DD;
        const float* b1_l  = b1  + (size_t)l * 4 * DD;
        const float* W2_l  = W2  + (size_t)l * 4 * DD * DD;
        const float* b2_l  = b2  + (size_t)l * DD;

        // LN1
        ln_kernel<<<TOK, 128>>>(x, ln1_g + l * DD, ln1_b + l * DD, xn);
        // Q and KV projections
        gemm_kernel<<<dim3(DD / 128, TOK / 128), 256>>>(xn, Wq_l,  bq_l,  nullptr, qb,  TOK, DD,     DD, 0);
        gemm_kernel<<<dim3(2 * DD / 128, TOK / 128), 256>>>(xn, Wkv_l, bkv_l, nullptr, kvb, TOK, 2 * DD, DD, 0);
        // windowed attention (roll/partition/mask/bias folded into indexing)
        attn_kernel<<<BATCH * (HH / WS) * (WW / WS) * NHEAD, 64>>>(qb, kvb, tbl_l, ao);
        // O projection + residual (in place on x)
        gemm_kernel<<<dim3(DD / 128, TOK / 128), 256>>>(ao, Wo_l, bo_l, x, x, TOK, DD, DD, 0);
        // LN2
        ln_kernel<<<TOK, 128>>>(x, ln2_g + l * DD, ln2_b + l * DD, hb);
        // MLP
        gemm_kernel<<<dim3(4 * DD / 128, TOK / 128), 256>>>(hb,  W1_l, b1_l, nullptr, hid, TOK, 4 * DD, DD, 1);
        gemm_kernel<<<dim3(DD / 128, TOK / 128), 256>>>(hid, W2_l, b2_l, x,       x,   TOK, DD, 4 * DD, 0);
    }
}

// round 6
// speedup vs baseline: 2.0934x; 2.0934x over previous
#include <cuda_runtime.h>
#include <cuda_bf16.h>
#include <math.h>
#include <stdint.h>

// Problem constants
#define BATCH 8
#define HH 64
#define WW 64
#define DD 512
#define NHEAD 16
#define DK 32
#define WS 8
#define SHIFT 4
#define TOK (BATCH*HH*WW)      // 32768
#define LAYERS 4
#define SCALE 0.17677669529663687f  // 1/sqrt(32)

// -------------------- scratch (allocation-free: __device__ globals) ------------
// bf16 "triple" activations: [hi | lo | hi] along K
__device__ __align__(128) unsigned short g_xn3 [ (size_t)TOK * 3 * DD ];       // 96 MB
__device__ __align__(128) unsigned short g_hb3 [ (size_t)TOK * 3 * DD ];       // 96 MB
__device__ __align__(128) unsigned short g_ao3 [ (size_t)TOK * 3 * DD ];       // 96 MB
__device__ __align__(128) unsigned short g_hid3[ (size_t)TOK * 3 * 4 * DD ];   // 384 MB
__device__ __align__(128) unsigned short g_w3  [ 37748736 ];                   // 72 MB
__device__ float g_q  [ (size_t)TOK * DD ];
__device__ float g_kv [ (size_t)TOK * 2 * DD ];

// ==================== helpers ==================================================
__device__ __forceinline__ uint32_t smem_u32(const void* p) {
    uint32_t a;
    asm("{ .reg .u64 t; cvta.to.shared.u64 t, %1; cvt.u32.u64 %0, t; }" : "=r"(a) : "l"(p));
    return a;
}
#define CP_ASYNC16(dst, src) \
    asm volatile("cp.async.cg.shared.global [%0], [%1], 16;" :: "r"(dst), "l"(src))
#define CP_COMMIT() asm volatile("cp.async.commit_group;" ::: "memory")
#define CP_WAIT1()  asm volatile("cp.async.wait_group 1;" ::: "memory")
#define CP_WAIT0()  asm volatile("cp.async.wait_group 0;" ::: "memory")

__device__ __forceinline__ void ldmx4(uint32_t& r0, uint32_t& r1, uint32_t& r2, uint32_t& r3,
                                      uint32_t addr) {
    asm volatile("ldmatrix.sync.aligned.m8n8.x4.shared.b16 {%0,%1,%2,%3}, [%4];"
                 : "=r"(r0), "=r"(r1), "=r"(r2), "=r"(r3) : "r"(addr));
}
__device__ __forceinline__ void mma16816(float* d, uint32_t a0, uint32_t a1, uint32_t a2,
                                         uint32_t a3, uint32_t b0, uint32_t b1) {
    asm volatile("mma.sync.aligned.m16n8k16.row.col.f32.bf16.bf16.f32 "
                 "{%0,%1,%2,%3},{%4,%5,%6,%7},{%8,%9},{%0,%1,%2,%3};"
                 : "+f"(d[0]), "+f"(d[1]), "+f"(d[2]), "+f"(d[3])
                 : "r"(a0), "r"(a1), "r"(a2), "r"(a3), "r"(b0), "r"(b1));
}

__device__ __forceinline__ unsigned short bf16hi(float v) {
    return __bfloat16_as_ushort(__float2bfloat16(v));
}
__device__ __forceinline__ void split_bf16(float v, unsigned short& hi, unsigned short& lo) {
    __nv_bfloat16 h = __float2bfloat16(v);
    hi = __bfloat16_as_ushort(h);
    lo = __bfloat16_as_ushort(__float2bfloat16(v - __bfloat162float(h)));
}
__device__ __forceinline__ float gelu_tanh(float x) {
    float x3 = x * x * x;
    return 0.5f * x * (1.0f + tanhf(0.7978845608028654f * (x + 0.044715f * x3)));
}

// ==================== weight convert: W[K,N] -> W3[N, 3K] = [Wh|Wh|Wl] =========
__global__ void convw_kernel(const float* __restrict__ src, unsigned short* __restrict__ dst,
                             int K, int N) {
    __shared__ float t[32][33];
    int n0 = blockIdx.x * 32, k0 = blockIdx.y * 32;
    src += (size_t)blockIdx.z * K * N;
    dst += (size_t)blockIdx.z * N * 3 * K;
    int tx = threadIdx.x, ty = threadIdx.y;
#pragma unroll
    for (int i = 0; i < 4; i++)
        t[ty + i * 8][tx] = src[(size_t)(k0 + ty + i * 8) * N + n0 + tx];
    __syncthreads();
#pragma unroll
    for (int i = 0; i < 4; i++) {
        int n = n0 + ty + i * 8;
        int k = k0 + tx;
        float v = t[tx][ty + i * 8];
        unsigned short hi, lo;
        split_bf16(v, hi, lo);
        size_t rb = (size_t)n * 3 * K;
        dst[rb + k] = hi;
        dst[rb + K + k] = hi;   // second block pairs with A_lo
        dst[rb + 2 * K + k] = lo;
    }
}
// NOTE block order: A3=[Ah|Al|Ah], W3=[Wh|Wh|Wl] -> Ah*Wh + Al*Wh + Ah*Wl. correct.

// ==================== LayerNorm -> bf16 triple =================================
__global__ __launch_bounds__(128) void ln_kernel(const float* __restrict__ x,
                                                 const float* __restrict__ gamma,
                                                 const float* __restrict__ beta,
                                                 unsigned short* __restrict__ out) {
    int tok = blockIdx.x;
    int tid = threadIdx.x;
    const float* xr = x + (size_t)tok * DD;
    float v[4];
#pragma unroll
    for (int i = 0; i < 4; i++) v[i] = xr[tid + i * 128];

    __shared__ float s1[4], s2[4];
    int lane = tid & 31, warp = tid >> 5;

    float s = v[0] + v[1] + v[2] + v[3];
#pragma unroll
    for (int o = 16; o > 0; o >>= 1) s += __shfl_xor_sync(0xffffffffu, s, o);
    if (lane == 0) s1[warp] = s;
    __syncthreads();
    float mean = (s1[0] + s1[1] + s1[2] + s1[3]) * (1.0f / DD);

    float sq = 0.f;
#pragma unroll
    for (int i = 0; i < 4; i++) { float d = v[i] - mean; sq += d * d; }
#pragma unroll
    for (int o = 16; o > 0; o >>= 1) sq += __shfl_xor_sync(0xffffffffu, sq, o);
    if (lane == 0) s2[warp] = sq;
    __syncthreads();
    float var = (s2[0] + s2[1] + s2[2] + s2[3]) * (1.0f / DD);
    float rs = rsqrtf(var + 1e-5f);

    unsigned short* orow = out + (size_t)tok * 3 * DD;
#pragma unroll
    for (int i = 0; i < 4; i++) {
        int c = tid + i * 128;
        float o = (v[i] - mean) * rs * gamma[c] + beta[c];
        unsigned short hi, lo;
        split_bf16(o, hi, lo);
        orow[c] = hi;
        orow[DD + c] = lo;
        orow[2 * DD + c] = hi;
    }
}

// ==================== bf16 mma GEMM ============================================
// C[M,N] = epilogue(A3[M,K3] @ W3[N,K3]^T)
// mode 0: fp32 out (+bias, +optional resid)   mode 1: gelu -> bf16 triple out
#define GBK 64
#define GSTAGES 3
#define GSTAGE_BYTES 32768     // A 16KB + B 16KB
#define GSB_OFF 16384
#define GEMM_SMEM (GSTAGES * GSTAGE_BYTES)

__global__ __launch_bounds__(256, 2) void gemm_mma(const unsigned short* __restrict__ A3,
                                                   const unsigned short* __restrict__ W3,
                                                   const float* __restrict__ bias,
                                                   const float* __restrict__ resid,
                                                   void* __restrict__ Cout,
                                                   int N, int K3, int mode) {
    extern __shared__ char smem[];
    uint32_t sb = smem_u32(smem);
    int tid = threadIdx.x, wid = tid >> 5, lane = tid & 31;
    int bm0 = blockIdx.y * 128, bn0 = blockIdx.x * 128;
    int wm = (wid & 3) * 32, wn = (wid >> 2) * 64;

    float acc[2][8][4];
#pragma unroll
    for (int t = 0; t < 2; t++)
#pragma unroll
        for (int n = 0; n < 8; n++)
#pragma unroll
            for (int r = 0; r < 4; r++) acc[t][n][r] = 0.f;

    int nch = K3 >> 6;

    // cp.async loader mapping: row = tid>>1 (0..127), chunks (tid&1)*4 .. +3
    int lr = tid >> 1;
    int lc0 = (tid & 1) * 4;
    const unsigned short* agp = A3 + (size_t)(bm0 + lr) * K3 + lc0 * 8;
    const unsigned short* bgp = W3 + (size_t)(bn0 + lr) * K3 + lc0 * 8;
    uint32_t sw[4];
#pragma unroll
    for (int it = 0; it < 4; it++)
        sw[it] = (uint32_t)lr * 128 + (uint32_t)(((lc0 + it) ^ (lr & 7)) << 4);

    // ldmatrix per-warp bases
    int arow[2], arx[2];
#pragma unroll
    for (int t = 0; t < 2; t++) {
        int r = wm + t * 16 + (lane & 15);
        arow[t] = r * 128;
        arx[t] = r & 7;
    }
    int ach = lane >> 4;
    int brow[4], brx[4];
#pragma unroll
    for (int p = 0; p < 4; p++) {
        int n = wn + p * 16 + (lane & 7) + ((lane >> 4) << 3);
        brow[p] = n * 128;
        brx[p] = n & 7;
    }
    int bch = (lane >> 3) & 1;

    // prologue: issue 2 stages
#pragma unroll
    for (int c = 0; c < 2; c++) {
        uint32_t st = sb + (uint32_t)c * GSTAGE_BYTES;
        const unsigned short* ag = agp + (size_t)c * GBK;
        const unsigned short* bg = bgp + (size_t)c * GBK;
#pragma unroll
        for (int it = 0; it < 4; it++) CP_ASYNC16(st + sw[it], ag + it * 8);
#pragma unroll
        for (int it = 0; it < 4; it++) CP_ASYNC16(st + GSB_OFF + sw[it], bg + it * 8);
        CP_COMMIT();
    }

    int buf = 0, nbuf = 2;
    for (int c = 0; c < nch; c++) {
        if (c == nch - 1) { CP_WAIT0(); } else { CP_WAIT1(); }
        __syncthreads();
        // prefetch chunk c+2 into freed buffer
        if (c + 2 < nch) {
            uint32_t st = sb + (uint32_t)nbuf * GSTAGE_BYTES;
            const unsigned short* ag = agp + (size_t)(c + 2) * GBK;
            const unsigned short* bg = bgp + (size_t)(c + 2) * GBK;
#pragma unroll
            for (int it = 0; it < 4; it++) CP_ASYNC16(st + sw[it], ag + it * 8);
#pragma unroll
            for (int it = 0; it < 4; it++) CP_ASYNC16(st + GSB_OFF + sw[it], bg + it * 8);
            CP_COMMIT();
        }
        uint32_t stA = sb + (uint32_t)buf * GSTAGE_BYTES;
        uint32_t stB = stA + GSB_OFF;
#pragma unroll
        for (int ks = 0; ks < 4; ks++) {
            uint32_t a[2][4];
#pragma unroll
            for (int t = 0; t < 2; t++) {
                uint32_t ad = stA + arow[t] + (uint32_t)((((ks << 1) + ach) ^ arx[t]) << 4);
                ldmx4(a[t][0], a[t][1], a[t][2], a[t][3], ad);
            }
            uint32_t b[4][4];
#pragma unroll
            for (int p = 0; p < 4; p++) {
                uint32_t bd = stB + brow[p] + (uint32_t)((((ks << 1) + bch) ^ brx[p]) << 4);
                ldmx4(b[p][0], b[p][1], b[p][2], b[p][3], bd);
            }
#pragma unroll
            for (int t = 0; t < 2; t++)
#pragma unroll
                for (int p = 0; p < 4; p++) {
                    mma16816(acc[t][2 * p],     a[t][0], a[t][1], a[t][2], a[t][3], b[p][0], b[p][1]);
                    mma16816(acc[t][2 * p + 1], a[t][0], a[t][1], a[t][2], a[t][3], b[p][2], b[p][3]);
                }
        }
        buf = (buf + 1 == GSTAGES) ? 0 : buf + 1;
        nbuf = (nbuf + 1 == GSTAGES) ? 0 : nbuf + 1;
        __syncthreads();
    }

    // epilogue
    int cbase = bn0 + wn;
#pragma unroll
    for (int t = 0; t < 2; t++) {
        int r0 = bm0 + wm + t * 16 + (lane >> 2);
#pragma unroll
        for (int half = 0; half < 2; half++) {
            int r = r0 + half * 8;
            if (mode == 0) {
                float* crow = (float*)Cout + (size_t)r * N + cbase;
                const float* rrow = resid ? resid + (size_t)r * N + cbase : (const float*)0;
#pragma unroll
                for (int p = 0; p < 8; p++) {
                    int c = p * 8 + (lane & 3) * 2;
                    float v0 = acc[t][p][half * 2 + 0] + bias[cbase + c];
                    float v1 = acc[t][p][half * 2 + 1] + bias[cbase + c + 1];
                    if (rrow) { v0 += rrow[c]; v1 += rrow[c + 1]; }
                    float2 o; o.x = v0; o.y = v1;
                    *(float2*)(crow + c) = o;
                }
            } else {
                unsigned short* orow = (unsigned short*)Cout + (size_t)r * 3 * N;
#pragma unroll
                for (int p = 0; p < 8; p++) {
                    int c = p * 8 + (lane & 3) * 2;
                    float v0 = gelu_tanh(acc[t][p][half * 2 + 0] + bias[cbase + c]);
                    float v1 = gelu_tanh(acc[t][p][half * 2 + 1] + bias[cbase + c + 1]);
                    unsigned short h0, l0, h1, l1;
                    split_bf16(v0, h0, l0);
                    split_bf16(v1, h1, l1);
                    uint32_t hp = (uint32_t)h0 | ((uint32_t)h1 << 16);
                    uint32_t lp = (uint32_t)l0 | ((uint32_t)l1 << 16);
                    int cn = cbase + c;
                    *(uint32_t*)(orow + cn) = hp;
                    *(uint32_t*)(orow + N + cn) = lp;
                    *(uint32_t*)(orow + 2 * N + cn) = hp;
                }
            }
        }
    }
}

// ==================== Shifted-window attention -> bf16 triple out ---------------
__device__ __forceinline__ int region_id(int hs, int ws) {
    int rh = (hs < HH - WS) ? 0 : (hs < HH - SHIFT) ? 1 : 2;
    int rw = (ws < WW - WS) ? 0 : (ws < WW - SHIFT) ? 1 : 2;
    return rh * 3 + rw;
}

__global__ __launch_bounds__(64) void attn_kernel(const float* __restrict__ q,
                                                  const float* __restrict__ kv,
                                                  const float* __restrict__ table,
                                                  unsigned short* __restrict__ out) {
    __shared__ float Ks[64 * 32];
    __shared__ float Vs[64 * 32];
    __shared__ float T[225];

    int bi = blockIdx.x;
    int nh  = bi & 15; bi >>= 4;
    int nww = bi & 7;  bi >>= 3;
    int nwh = bi & 7;  bi >>= 3;
    int b = bi;
    int tid = threadIdx.x;

    for (int i = tid; i < 225; i += 64) T[i] = table[i * NHEAD + nh];

    for (int idx = tid; idx < 512; idx += 64) {
        int e = idx >> 3, d4 = (idx & 7) << 2;
        int h = (nwh * WS + (e >> 3) + SHIFT) & (HH - 1);
        int w = (nww * WS + (e & 7) + SHIFT) & (WW - 1);
        size_t tok = ((size_t)b * HH + h) * WW + w;
        float4 kk = *(const float4*)(kv + tok * (2 * DD) + nh * DK + d4);
        float4 vv = *(const float4*)(kv + tok * (2 * DD) + DD + nh * DK + d4);
        *(float4*)(Ks + e * 32 + d4) = kk;
        *(float4*)(Vs + e * 32 + d4) = vv;
    }
    __syncthreads();

    int iq = tid >> 3, jq = tid & 7;
    int h = (nwh * WS + iq + SHIFT) & (HH - 1);
    int w = (nww * WS + jq + SHIFT) & (WW - 1);
    size_t tok = ((size_t)b * HH + h) * WW + w;

    float qr[DK];
#pragma unroll
    for (int d = 0; d < DK; d += 4)
        *(float4*)(qr + d) = *(const float4*)(q + tok * DD + nh * DK + d);

    int cq = region_id(nwh * WS + iq, nww * WS + jq);

    float sreg[64];
    float rowmax = -1e30f;
#pragma unroll 4
    for (int k = 0; k < 64; k++) {
        int ik = k >> 3, jk = k & 7;
        float dot = 0.f;
#pragma unroll
        for (int d = 0; d < DK; d++) dot += qr[d] * Ks[k * 32 + d];
        float s = dot * SCALE + T[(iq - ik + 7) * 15 + (jq - jk + 7)];
        int ck = region_id(nwh * WS + ik, nww * WS + jk);
        if (ck != cq) s = -1e9f;
        sreg[k] = s;
        rowmax = fmaxf(rowmax, s);
    }

    float denom = 0.f;
#pragma unroll
    for (int k = 0; k < 64; k++) {
        float e = expf(sreg[k] - rowmax);
        sreg[k] = e;
        denom += e;
    }
    float inv = 1.0f / denom;

    float accv[DK];
#pragma unroll
    for (int d = 0; d < DK; d++) accv[d] = 0.f;
#pragma unroll 4
    for (int k = 0; k < 64; k++) {
        float a = sreg[k];
#pragma unroll
        for (int d = 0; d < DK; d++) accv[d] += a * Vs[k * 32 + d];
    }

    unsigned short* orow = out + tok * 3 * DD + nh * DK;
#pragma unroll
    for (int d = 0; d < DK; d += 2) {
        unsigned short h0, l0, h1, l1;
        split_bf16(accv[d] * inv, h0, l0);
        split_bf16(accv[d + 1] * inv, h1, l1);
        uint32_t hp = (uint32_t)h0 | ((uint32_t)h1 << 16);
        uint32_t lp = (uint32_t)l0 | ((uint32_t)l1 << 16);
        *(uint32_t*)(orow + d) = hp;
        *(uint32_t*)(orow + DD + d) = lp;
        *(uint32_t*)(orow + 2 * DD + d) = hp;
    }
}

// ==================== driver ===================================================
extern "C" void kernel_launch(void* const* d_in, const int* in_sizes, int n_in,
                              void* d_out, int out_size) {
    const float* x_in      = (const float*)d_in[0];
    const float* Wq        = (const float*)d_in[3];
    const float* bq        = (const float*)d_in[4];
    const float* Wkv       = (const float*)d_in[5];
    const float* bkv       = (const float*)d_in[6];
    const float* Wo        = (const float*)d_in[7];
    const float* bo        = (const float*)d_in[8];
    const float* rel_table = (const float*)d_in[9];
    const float* ln1_g     = (const float*)d_in[10];
    const float* ln1_b     = (const float*)d_in[11];
    const float* ln2_g     = (const float*)d_in[12];
    const float* ln2_b     = (const float*)d_in[13];
    const float* W1        = (const float*)d_in[14];
    const float* b1        = (const float*)d_in[15];
    const float* W2        = (const float*)d_in[16];
    const float* b2        = (const float*)d_in[17];

    float* x = (float*)d_out;

    unsigned short *xn3, *hb3, *ao3, *hid3, *w3;
    float *qb, *kvb;
    cudaGetSymbolAddress((void**)&xn3,  g_xn3);
    cudaGetSymbolAddress((void**)&hb3,  g_hb3);
    cudaGetSymbolAddress((void**)&ao3,  g_ao3);
    cudaGetSymbolAddress((void**)&hid3, g_hid3);
    cudaGetSymbolAddress((void**)&w3,   g_w3);
    cudaGetSymbolAddress((void**)&qb,   g_q);
    cudaGetSymbolAddress((void**)&kvb,  g_kv);

    cudaFuncSetAttribute(gemm_mma, cudaFuncAttributeMaxDynamicSharedMemorySize, GEMM_SMEM);

    // w3 layout offsets (elements), per-weight blocks of [L][N][3K]
    const size_t off_q  = 0;                          // 4 * 512*1536
    const size_t off_kv = off_q  + (size_t)4 * 512 * 1536;
    const size_t off_o  = off_kv + (size_t)4 * 1024 * 1536;
    const size_t off_1  = off_o  + (size_t)4 * 512 * 1536;
    const size_t off_2  = off_1  + (size_t)4 * 2048 * 1536;

    dim3 tb(32, 8);
    convw_kernel<<<dim3(512 / 32,  512 / 32,  LAYERS), tb>>>(Wq,  w3 + off_q,  512,  512);
    convw_kernel<<<dim3(1024 / 32, 512 / 32,  LAYERS), tb>>>(Wkv, w3 + off_kv, 512,  1024);
    convw_kernel<<<dim3(512 / 32,  512 / 32,  LAYERS), tb>>>(Wo,  w3 + off_o,  512,  512);
    convw_kernel<<<dim3(2048 / 32, 512 / 32,  LAYERS), tb>>>(W1,  w3 + off_1,  512,  2048);
    convw_kernel<<<dim3(512 / 32,  2048 / 32, LAYERS), tb>>>(W2,  w3 + off_2,  2048, 512);

    cudaMemcpyAsync(x, x_in, (size_t)TOK * DD * sizeof(float),
                    cudaMemcpyDeviceToDevice, 0);

    for (int l = 0; l < LAYERS; l++) {
        const unsigned short* wq3 = w3 + off_q  + (size_t)l * 512 * 1536;
        const unsigned short* wk3 = w3 + off_kv + (size_t)l * 1024 * 1536;
        const unsigned short* wo3 = w3 + off_o  + (size_t)l * 512 * 1536;
        const unsigned short* w13 = w3 + off_1  + (size_t)l * 2048 * 1536;
        const unsigned short* w23 = w3 + off_2  + (size_t)l * 512 * 6144;
        const float* bq_l  = bq  + (size_t)l * DD;
        const float* bkv_l = bkv + (size_t)l * 2 * DD;
        const float* bo_l  = bo  + (size_t)l * DD;
        const float* tbl_l = rel_table + (size_t)l * 225 * NHEAD;
        const float* b1_l  = b1  + (size_t)l * 4 * DD;
        const float* b2_l  = b2  + (size_t)l * DD;

        ln_kernel<<<TOK, 128>>>(x, ln1_g + l * DD, ln1_b + l * DD, xn3);
        gemm_mma<<<dim3(512 / 128, TOK / 128), 256, GEMM_SMEM>>>(
            xn3, wq3, bq_l, nullptr, qb, 512, 1536, 0);
        gemm_mma<<<dim3(1024 / 128, TOK / 128), 256, GEMM_SMEM>>>(
            xn3, wk3, bkv_l, nullptr, kvb, 1024, 1536, 0);
        attn_kernel<<<BATCH * (HH / WS) * (WW / WS) * NHEAD, 64>>>(qb, kvb, tbl_l, ao3);
        gemm_mma<<<dim3(512 / 128, TOK / 128), 256, GEMM_SMEM>>>(
            ao3, wo3, bo_l, x, x, 512, 1536, 0);
        ln_kernel<<<TOK, 128>>>(x, ln2_g + l * DD, ln2_b + l * DD, hb3);
        gemm_mma<<<dim3(2048 / 128, TOK / 128), 256, GEMM_SMEM>>>(
            hb3, w13, b1_l, nullptr, hid3, 2048, 1536, 1);
        gemm_mma<<<dim3(512 / 128, TOK / 128), 256, GEMM_SMEM>>>(
            hid3, w23, b2_l, x, x, 512, 6144, 0);
    }
}

// round 7
// speedup vs baseline: 2.1694x; 1.0363x over previous
#include <cuda_runtime.h>
#include <cuda_bf16.h>
#include <math.h>
#include <stdint.h>

// Problem constants
#define BATCH 8
#define HH 64
#define WW 64
#define DD 512
#define NHEAD 16
#define DK 32
#define WS 8
#define SHIFT 4
#define TOK (BATCH*HH*WW)      // 32768
#define LAYERS 4
#define SCALE 0.17677669529663687f  // 1/sqrt(32)

// -------------------- scratch (allocation-free: __device__ globals) ------------
// bf16 "pair" activations: [hi | lo] along K (row stride 2K)
__device__ __align__(128) unsigned short g_xn2 [ (size_t)TOK * 2 * DD ];       // 64 MB
__device__ __align__(128) unsigned short g_hb2 [ (size_t)TOK * 2 * DD ];       // 64 MB
__device__ __align__(128) unsigned short g_ao2 [ (size_t)TOK * 2 * DD ];       // 64 MB
__device__ __align__(128) unsigned short g_hid2[ (size_t)TOK * 2 * 4 * DD ];   // 256 MB
__device__ __align__(128) unsigned short g_w3  [ 37748736 ];                   // 72 MB  [N][3K]=[Wh|Wh|Wl]
__device__ float g_q  [ (size_t)TOK * DD ];
__device__ float g_kv [ (size_t)TOK * 2 * DD ];

// ==================== helpers ==================================================
__device__ __forceinline__ uint32_t smem_u32(const void* p) {
    uint32_t a;
    asm("{ .reg .u64 t; cvta.to.shared.u64 t, %1; cvt.u32.u64 %0, t; }" : "=r"(a) : "l"(p));
    return a;
}
#define CP_ASYNC16(dst, src) \
    asm volatile("cp.async.cg.shared.global [%0], [%1], 16;" :: "r"(dst), "l"(src))
#define CP_COMMIT() asm volatile("cp.async.commit_group;" ::: "memory")
#define CP_WAIT1()  asm volatile("cp.async.wait_group 1;" ::: "memory")
#define CP_WAIT0()  asm volatile("cp.async.wait_group 0;" ::: "memory")

__device__ __forceinline__ void ldmx4(uint32_t& r0, uint32_t& r1, uint32_t& r2, uint32_t& r3,
                                      uint32_t addr) {
    asm volatile("ldmatrix.sync.aligned.m8n8.x4.shared.b16 {%0,%1,%2,%3}, [%4];"
                 : "=r"(r0), "=r"(r1), "=r"(r2), "=r"(r3) : "r"(addr));
}
__device__ __forceinline__ void mma16816(float* d, uint32_t a0, uint32_t a1, uint32_t a2,
                                         uint32_t a3, uint32_t b0, uint32_t b1) {
    asm volatile("mma.sync.aligned.m16n8k16.row.col.f32.bf16.bf16.f32 "
                 "{%0,%1,%2,%3},{%4,%5,%6,%7},{%8,%9},{%0,%1,%2,%3};"
                 : "+f"(d[0]), "+f"(d[1]), "+f"(d[2]), "+f"(d[3])
                 : "r"(a0), "r"(a1), "r"(a2), "r"(a3), "r"(b0), "r"(b1));
}

__device__ __forceinline__ void split_bf16(float v, unsigned short& hi, unsigned short& lo) {
    __nv_bfloat16 h = __float2bfloat16(v);
    hi = __bfloat16_as_ushort(h);
    lo = __bfloat16_as_ushort(__float2bfloat16(v - __bfloat162float(h)));
}
__device__ __forceinline__ float gelu_tanh(float x) {
    float x3 = x * x * x;
    return 0.5f * x * (1.0f + tanhf(0.7978845608028654f * (x + 0.044715f * x3)));
}

// ==================== weight convert: W[K,N] -> W3[N, 3K] = [Wh|Wh|Wl] =========
__global__ void convw_kernel(const float* __restrict__ src, unsigned short* __restrict__ dst,
                             int K, int N) {
    __shared__ float t[32][33];
    int n0 = blockIdx.x * 32, k0 = blockIdx.y * 32;
    src += (size_t)blockIdx.z * K * N;
    dst += (size_t)blockIdx.z * N * 3 * K;
    int tx = threadIdx.x, ty = threadIdx.y;
#pragma unroll
    for (int i = 0; i < 4; i++)
        t[ty + i * 8][tx] = src[(size_t)(k0 + ty + i * 8) * N + n0 + tx];
    __syncthreads();
#pragma unroll
    for (int i = 0; i < 4; i++) {
        int n = n0 + ty + i * 8;
        int k = k0 + tx;
        float v = t[tx][ty + i * 8];
        unsigned short hi, lo;
        split_bf16(v, hi, lo);
        size_t rb = (size_t)n * 3 * K;
        dst[rb + k] = hi;
        dst[rb + K + k] = hi;   // pairs with A_lo
        dst[rb + 2 * K + k] = lo;
    }
}
// K-schedule: A chunks [Ah|Al|Ah(remapped)] x W chunks [Wh|Wh|Wl]
//   = Ah*Wh + Al*Wh + Ah*Wl  (lo*lo dropped, ~2^-18 rel)

// ==================== LayerNorm -> bf16 pair ===================================
__global__ __launch_bounds__(128) void ln_kernel(const float* __restrict__ x,
                                                 const float* __restrict__ gamma,
                                                 const float* __restrict__ beta,
                                                 unsigned short* __restrict__ out) {
    int tok = blockIdx.x;
    int tid = threadIdx.x;
    const float* xr = x + (size_t)tok * DD;
    float v[4];
#pragma unroll
    for (int i = 0; i < 4; i++) v[i] = xr[tid + i * 128];

    __shared__ float s1[4], s2[4];
    int lane = tid & 31, warp = tid >> 5;

    float s = v[0] + v[1] + v[2] + v[3];
#pragma unroll
    for (int o = 16; o > 0; o >>= 1) s += __shfl_xor_sync(0xffffffffu, s, o);
    if (lane == 0) s1[warp] = s;
    __syncthreads();
    float mean = (s1[0] + s1[1] + s1[2] + s1[3]) * (1.0f / DD);

    float sq = 0.f;
#pragma unroll
    for (int i = 0; i < 4; i++) { float d = v[i] - mean; sq += d * d; }
#pragma unroll
    for (int o = 16; o > 0; o >>= 1) sq += __shfl_xor_sync(0xffffffffu, sq, o);
    if (lane == 0) s2[warp] = sq;
    __syncthreads();
    float var = (s2[0] + s2[1] + s2[2] + s2[3]) * (1.0f / DD);
    float rs = rsqrtf(var + 1e-5f);

    unsigned short* orow = out + (size_t)tok * 2 * DD;
#pragma unroll
    for (int i = 0; i < 4; i++) {
        int c = tid + i * 128;
        float o = (v[i] - mean) * rs * gamma[c] + beta[c];
        unsigned short hi, lo;
        split_bf16(o, hi, lo);
        orow[c] = hi;
        orow[DD + c] = lo;
    }
}

// ==================== bf16 mma GEMM ============================================
// C[M,N] = epilogue(A2[M,2K] (3-pass schedule) @ W3[N,3K]^T)
// mode 0: fp32 out (+bias, +optional resid)   mode 1: gelu -> bf16 pair out
#define GBK 64
#define GSTAGES 3
#define GSTAGE_BYTES 32768     // A 16KB + B 16KB
#define GSB_OFF 16384
#define GEMM_SMEM (GSTAGES * GSTAGE_BYTES)

__global__ __launch_bounds__(256, 2) void gemm_mma(const unsigned short* __restrict__ A2,
                                                   const unsigned short* __restrict__ W3,
                                                   const float* __restrict__ bias,
                                                   const float* __restrict__ resid,
                                                   void* __restrict__ Cout,
                                                   int N, int K, int mode) {
    extern __shared__ char smem[];
    uint32_t sb = smem_u32(smem);
    int tid = threadIdx.x, wid = tid >> 5, lane = tid & 31;
    int bm0 = blockIdx.y * 128, bn0 = blockIdx.x * 128;
    int wm = (wid & 3) * 32, wn = (wid >> 2) * 64;

    float acc[2][8][4];
#pragma unroll
    for (int t = 0; t < 2; t++)
#pragma unroll
        for (int n = 0; n < 8; n++)
#pragma unroll
            for (int r = 0; r < 4; r++) acc[t][n][r] = 0.f;

    const int nc2 = (2 * K) >> 6;     // A pair chunks
    const int nch = (3 * K) >> 6;     // total schedule chunks

    // cp.async loader mapping: row = tid>>1 (0..127), 4 x 16B chunks at (tid&1)*4
    int lr = tid >> 1;
    int lc0 = (tid & 1) * 4;
    const unsigned short* agp = A2 + (size_t)(bm0 + lr) * (2 * K) + lc0 * 8;
    const unsigned short* bgp = W3 + (size_t)(bn0 + lr) * (3 * K) + lc0 * 8;
    uint32_t sw[4];
#pragma unroll
    for (int it = 0; it < 4; it++)
        sw[it] = (uint32_t)lr * 128 + (uint32_t)(((lc0 + it) ^ (lr & 7)) << 4);

    // ldmatrix per-warp bases
    int arow[2], arx[2];
#pragma unroll
    for (int t = 0; t < 2; t++) {
        int r = wm + t * 16 + (lane & 15);
        arow[t] = r * 128;
        arx[t] = r & 7;
    }
    int ach = lane >> 4;
    int brow[4], brx[4];
#pragma unroll
    for (int p = 0; p < 4; p++) {
        int n = wn + p * 16 + (lane & 7) + ((lane >> 4) << 3);
        brow[p] = n * 128;
        brx[p] = n & 7;
    }
    int bch = (lane >> 3) & 1;

    // stage issue helper (A chunk remapped: third pass reuses Ah block)
    auto issue_stage = [&](int c, int stage) {
        uint32_t st = sb + (uint32_t)stage * GSTAGE_BYTES;
        int ca = (c < nc2) ? c : c - nc2;
        const unsigned short* ag = agp + (size_t)ca * GBK;
        const unsigned short* bg = bgp + (size_t)c * GBK;
#pragma unroll
        for (int it = 0; it < 4; it++) CP_ASYNC16(st + sw[it], ag + it * 8);
#pragma unroll
        for (int it = 0; it < 4; it++) CP_ASYNC16(st + GSB_OFF + sw[it], bg + it * 8);
        CP_COMMIT();
    };

    issue_stage(0, 0);
    issue_stage(1, 1);

    int buf = 0, nbuf = 2;
    for (int c = 0; c < nch; c++) {
        if (c == nch - 1) { CP_WAIT0(); } else { CP_WAIT1(); }
        __syncthreads();
        if (c + 2 < nch) issue_stage(c + 2, nbuf);

        uint32_t stA = sb + (uint32_t)buf * GSTAGE_BYTES;
        uint32_t stB = stA + GSB_OFF;
#pragma unroll
        for (int ks = 0; ks < 4; ks++) {
            uint32_t a0[4], a1[4];
            {
                uint32_t ad0 = stA + arow[0] + (uint32_t)((((ks << 1) + ach) ^ arx[0]) << 4);
                ldmx4(a0[0], a0[1], a0[2], a0[3], ad0);
                uint32_t ad1 = stA + arow[1] + (uint32_t)((((ks << 1) + ach) ^ arx[1]) << 4);
                ldmx4(a1[0], a1[1], a1[2], a1[3], ad1);
            }
#pragma unroll
            for (int p = 0; p < 4; p++) {
                uint32_t b0, b1, b2, b3;
                uint32_t bd = stB + brow[p] + (uint32_t)((((ks << 1) + bch) ^ brx[p]) << 4);
                ldmx4(b0, b1, b2, b3, bd);
                mma16816(acc[0][2 * p],     a0[0], a0[1], a0[2], a0[3], b0, b1);
                mma16816(acc[0][2 * p + 1], a0[0], a0[1], a0[2], a0[3], b2, b3);
                mma16816(acc[1][2 * p],     a1[0], a1[1], a1[2], a1[3], b0, b1);
                mma16816(acc[1][2 * p + 1], a1[0], a1[1], a1[2], a1[3], b2, b3);
            }
        }
        buf = (buf + 1 == GSTAGES) ? 0 : buf + 1;
        nbuf = (nbuf + 1 == GSTAGES) ? 0 : nbuf + 1;
        __syncthreads();
    }

    // epilogue
    int cbase = bn0 + wn;
#pragma unroll
    for (int t = 0; t < 2; t++) {
        int r0 = bm0 + wm + t * 16 + (lane >> 2);
#pragma unroll
        for (int half = 0; half < 2; half++) {
            int r = r0 + half * 8;
            if (mode == 0) {
                float* crow = (float*)Cout + (size_t)r * N + cbase;
                const float* rrow = resid ? resid + (size_t)r * N + cbase : (const float*)0;
#pragma unroll
                for (int p = 0; p < 8; p++) {
                    int c = p * 8 + (lane & 3) * 2;
                    float v0 = acc[t][p][half * 2 + 0] + bias[cbase + c];
                    float v1 = acc[t][p][half * 2 + 1] + bias[cbase + c + 1];
                    if (rrow) { v0 += rrow[c]; v1 += rrow[c + 1]; }
                    float2 o; o.x = v0; o.y = v1;
                    *(float2*)(crow + c) = o;
                }
            } else {
                unsigned short* orow = (unsigned short*)Cout + (size_t)r * 2 * N;
#pragma unroll
                for (int p = 0; p < 8; p++) {
                    int c = p * 8 + (lane & 3) * 2;
                    float v0 = gelu_tanh(acc[t][p][half * 2 + 0] + bias[cbase + c]);
                    float v1 = gelu_tanh(acc[t][p][half * 2 + 1] + bias[cbase + c + 1]);
                    unsigned short h0, l0, h1, l1;
                    split_bf16(v0, h0, l0);
                    split_bf16(v1, h1, l1);
                    int cn = cbase + c;
                    *(uint32_t*)(orow + cn)     = (uint32_t)h0 | ((uint32_t)h1 << 16);
                    *(uint32_t*)(orow + N + cn) = (uint32_t)l0 | ((uint32_t)l1 << 16);
                }
            }
        }
    }
}

// ==================== Shifted-window attention -> bf16 pair out ----------------
__device__ __forceinline__ int region_id(int hs, int ws) {
    int rh = (hs < HH - WS) ? 0 : (hs < HH - SHIFT) ? 1 : 2;
    int rw = (ws < WW - WS) ? 0 : (ws < WW - SHIFT) ? 1 : 2;
    return rh * 3 + rw;
}

// 128 threads = 2 heads x 64 queries per block
__global__ __launch_bounds__(128) void attn_kernel(const float* __restrict__ q,
                                                   const float* __restrict__ kv,
                                                   const float* __restrict__ table,
                                                   unsigned short* __restrict__ out) {
    __shared__ float Ks[2][64 * 32];
    __shared__ float Vs[2][64 * 32];
    __shared__ float T[2][225];

    int bi = blockIdx.x;
    int nhp = bi & 7;  bi >>= 3;     // head pair
    int nww = bi & 7;  bi >>= 3;
    int nwh = bi & 7;  bi >>= 3;
    int b = bi;
    int tid = threadIdx.x;
    int hs = tid >> 6;               // head slot 0/1
    int t6 = tid & 63;
    int nh = nhp * 2 + hs;

    for (int i = t6; i < 225; i += 64) T[hs][i] = table[i * NHEAD + nh];

    for (int idx = t6; idx < 512; idx += 64) {
        int e = idx >> 3, d4 = (idx & 7) << 2;
        int h = (nwh * WS + (e >> 3) + SHIFT) & (HH - 1);
        int w = (nww * WS + (e & 7) + SHIFT) & (WW - 1);
        size_t tok = ((size_t)b * HH + h) * WW + w;
        float4 kk = *(const float4*)(kv + tok * (2 * DD) + nh * DK + d4);
        float4 vv = *(const float4*)(kv + tok * (2 * DD) + DD + nh * DK + d4);
        *(float4*)(Ks[hs] + e * 32 + d4) = kk;
        *(float4*)(Vs[hs] + e * 32 + d4) = vv;
    }
    __syncthreads();

    int iq = t6 >> 3, jq = t6 & 7;
    int h = (nwh * WS + iq + SHIFT) & (HH - 1);
    int w = (nww * WS + jq + SHIFT) & (WW - 1);
    size_t tok = ((size_t)b * HH + h) * WW + w;

    float qr[DK];
#pragma unroll
    for (int d = 0; d < DK; d += 4)
        *(float4*)(qr + d) = *(const float4*)(q + tok * DD + nh * DK + d);

    int cq = region_id(nwh * WS + iq, nww * WS + jq);

    float sreg[64];
    float rowmax = -1e30f;
#pragma unroll 4
    for (int k = 0; k < 64; k++) {
        int ik = k >> 3, jk = k & 7;
        float dot = 0.f;
#pragma unroll
        for (int d = 0; d < DK; d++) dot += qr[d] * Ks[hs][k * 32 + d];
        float s = dot * SCALE + T[hs][(iq - ik + 7) * 15 + (jq - jk + 7)];
        int ck = region_id(nwh * WS + ik, nww * WS + jk);
        if (ck != cq) s = -1e9f;
        sreg[k] = s;
        rowmax = fmaxf(rowmax, s);
    }

    float denom = 0.f;
#pragma unroll
    for (int k = 0; k < 64; k++) {
        float e = expf(sreg[k] - rowmax);
        sreg[k] = e;
        denom += e;
    }
    float inv = 1.0f / denom;

    float accv[DK];
#pragma unroll
    for (int d = 0; d < DK; d++) accv[d] = 0.f;
#pragma unroll 4
    for (int k = 0; k < 64; k++) {
        float a = sreg[k];
#pragma unroll
        for (int d = 0; d < DK; d++) accv[d] += a * Vs[hs][k * 32 + d];
    }

    unsigned short* orow = out + tok * 2 * DD + nh * DK;
#pragma unroll
    for (int d = 0; d < DK; d += 2) {
        unsigned short h0, l0, h1, l1;
        split_bf16(accv[d] * inv, h0, l0);
        split_bf16(accv[d + 1] * inv, h1, l1);
        *(uint32_t*)(orow + d)      = (uint32_t)h0 | ((uint32_t)h1 << 16);
        *(uint32_t*)(orow + DD + d) = (uint32_t)l0 | ((uint32_t)l1 << 16);
    }
}

// ==================== driver ===================================================
extern "C" void kernel_launch(void* const* d_in, const int* in_sizes, int n_in,
                              void* d_out, int out_size) {
    const float* x_in      = (const float*)d_in[0];
    const float* Wq        = (const float*)d_in[3];
    const float* bq        = (const float*)d_in[4];
    const float* Wkv       = (const float*)d_in[5];
    const float* bkv       = (const float*)d_in[6];
    const float* Wo        = (const float*)d_in[7];
    const float* bo        = (const float*)d_in[8];
    const float* rel_table = (const float*)d_in[9];
    const float* ln1_g     = (const float*)d_in[10];
    const float* ln1_b     = (const float*)d_in[11];
    const float* ln2_g     = (const float*)d_in[12];
    const float* ln2_b     = (const float*)d_in[13];
    const float* W1        = (const float*)d_in[14];
    const float* b1        = (const float*)d_in[15];
    const float* W2        = (const float*)d_in[16];
    const float* b2        = (const float*)d_in[17];

    float* x = (float*)d_out;

    unsigned short *xn2, *hb2, *ao2, *hid2, *w3;
    float *qb, *kvb;
    cudaGetSymbolAddress((void**)&xn2,  g_xn2);
    cudaGetSymbolAddress((void**)&hb2,  g_hb2);
    cudaGetSymbolAddress((void**)&ao2,  g_ao2);
    cudaGetSymbolAddress((void**)&hid2, g_hid2);
    cudaGetSymbolAddress((void**)&w3,   g_w3);
    cudaGetSymbolAddress((void**)&qb,   g_q);
    cudaGetSymbolAddress((void**)&kvb,  g_kv);

    cudaFuncSetAttribute(gemm_mma, cudaFuncAttributeMaxDynamicSharedMemorySize, GEMM_SMEM);

    // w3 layout offsets (elements), per-weight blocks of [L][N][3K]
    const size_t off_q  = 0;
    const size_t off_kv = off_q  + (size_t)4 * 512 * 1536;
    const size_t off_o  = off_kv + (size_t)4 * 1024 * 1536;
    const size_t off_1  = off_o  + (size_t)4 * 512 * 1536;
    const size_t off_2  = off_1  + (size_t)4 * 2048 * 1536;

    dim3 tb(32, 8);
    convw_kernel<<<dim3(512 / 32,  512 / 32,  LAYERS), tb>>>(Wq,  w3 + off_q,  512,  512);
    convw_kernel<<<dim3(1024 / 32, 512 / 32,  LAYERS), tb>>>(Wkv, w3 + off_kv, 512,  1024);
    convw_kernel<<<dim3(512 / 32,  512 / 32,  LAYERS), tb>>>(Wo,  w3 + off_o,  512,  512);
    convw_kernel<<<dim3(2048 / 32, 512 / 32,  LAYERS), tb>>>(W1,  w3 + off_1,  512,  2048);
    convw_kernel<<<dim3(512 / 32,  2048 / 32, LAYERS), tb>>>(W2,  w3 + off_2,  2048, 512);

    cudaMemcpyAsync(x, x_in, (size_t)TOK * DD * sizeof(float),
                    cudaMemcpyDeviceToDevice, 0);

    for (int l = 0; l < LAYERS; l++) {
        const unsigned short* wq3 = w3 + off_q  + (size_t)l * 512 * 1536;
        const unsigned short* wk3 = w3 + off_kv + (size_t)l * 1024 * 1536;
        const unsigned short* wo3 = w3 + off_o  + (size_t)l * 512 * 1536;
        const unsigned short* w13 = w3 + off_1  + (size_t)l * 2048 * 1536;
        const unsigned short* w23 = w3 + off_2  + (size_t)l * 512 * 6144;
        const float* bq_l  = bq  + (size_t)l * DD;
        const float* bkv_l = bkv + (size_t)l * 2 * DD;
        const float* bo_l  = bo  + (size_t)l * DD;
        const float* tbl_l = rel_table + (size_t)l * 225 * NHEAD;
        const float* b1_l  = b1  + (size_t)l * 4 * DD;
        const float* b2_l  = b2  + (size_t)l * DD;

        ln_kernel<<<TOK, 128>>>(x, ln1_g + l * DD, ln1_b + l * DD, xn2);
        gemm_mma<<<dim3(512 / 128, TOK / 128), 256, GEMM_SMEM>>>(
            xn2, wq3, bq_l, nullptr, qb, 512, 512, 0);
        gemm_mma<<<dim3(1024 / 128, TOK / 128), 256, GEMM_SMEM>>>(
            xn2, wk3, bkv_l, nullptr, kvb, 1024, 512, 0);
        attn_kernel<<<BATCH * 8 * 8 * (NHEAD / 2), 128>>>(qb, kvb, tbl_l, ao2);
        gemm_mma<<<dim3(512 / 128, TOK / 128), 256, GEMM_SMEM>>>(
            ao2, wo3, bo_l, x, x, 512, 512, 0);
        ln_kernel<<<TOK, 128>>>(x, ln2_g + l * DD, ln2_b + l * DD, hb2);
        gemm_mma<<<dim3(2048 / 128, TOK / 128), 256, GEMM_SMEM>>>(
            hb2, w13, b1_l, nullptr, hid2, 2048, 512, 1);
        gemm_mma<<<dim3(512 / 128, TOK / 128), 256, GEMM_SMEM>>>(
            hid2, w23, b2_l, x, x, 512, 2048, 0);
    }
}